// round 2
// baseline (speedup 1.0000x reference)
#include <cuda_runtime.h>
#include <cuda_bf16.h>
#include <cstdint>

// TiThTe: B independent 3-state RC thermal models, sequential scan over T steps.
// state: [T_in, T_heater, T_env]; params per row: C1,R1,C2,R2,C3,R3.
//   P_in2Wall   = (T_in - T_env)   / R1
//   P_in2Heater = (T_in - T_heater)/ R2
//   dT_in     = (solar - P_in2Wall - P_in2Heater) * dt/C1
//   dT_heater = (heat + P_in2Heater) * dt/C2
//   dT_env    = (P_in2Wall + (T_out - T_env)/R3) * dt/C3
//   state += tame(dT),  tame(x) = x*TAME / sqrt(x^2 + TAME^2)
//
// Strategy: one thread per system (B=4096 -> 128 warps). Latency-bound on the
// per-step dependent chain; hoist all constants, prefetch + premultiply the
// next step's forcing terms off the critical path, MUFU rsqrt for tame.

#define TAME_C  100000.0f
#define TAME_SQ 1.0e10f

__device__ __forceinline__ float rsq_approx(float x) {
    float y;
    asm("rsqrt.approx.f32 %0, %1;" : "=f"(y) : "f"(x));
    return y;
}

__global__ void __launch_bounds__(32, 1)
tithte_kernel(const float* __restrict__ state0,
              const float* __restrict__ params,
              const float* __restrict__ ext,     // (T,3): T_out, heatPower, solarGains
              const int*   __restrict__ dtp,
              float* __restrict__ out,           // (T,B,3)
              int B, int T)
{
    int b = blockIdx.x * blockDim.x + threadIdx.x;
    if (b >= B) return;

    // dt may arrive as int32(60) or float32(60.0f); both decode to 60.0f.
    int dv = dtp[0];
    float dtf = (dv > 0 && dv < (1 << 23)) ? (float)dv : __int_as_float(dv);

    float Tin = state0[b * 3 + 0];
    float Th  = state0[b * 3 + 1];
    float Te  = state0[b * 3 + 2];

    float C1 = params[b * 6 + 0], R1 = params[b * 6 + 1];
    float C2 = params[b * 6 + 2], R2 = params[b * 6 + 3];
    float C3 = params[b * 6 + 4], R3 = params[b * 6 + 5];

    // Hoisted combined constants.
    float k1  = dtf / C1;          // multiplies solarGains
    float nkA = -k1 / R1;          // * (T_in - T_env)      in dT_in
    float nkB = -k1 / R2;          // * (T_in - T_heater)   in dT_in
    float k2  = dtf / C2;          // multiplies heatPower
    float kC  =  k2 / R2;          // * (T_in - T_heater)   in dT_heater
    float k3  = dtf / C3;
    float kD  =  k3 / R1;          // * (T_in - T_env)      in dT_env
    float kE  =  k3 / R3;          // * (T_out - T_env)     in dT_env

    // Forcing terms for step 0, premultiplied (off the dependent chain).
    float To = __ldg(ext + 0);
    float sk = __ldg(ext + 2) * k1;   // solar * dt/C1
    float hk = __ldg(ext + 1) * k2;   // heat  * dt/C2

    float* op = out + (size_t)b * 3;
    const size_t stride = (size_t)B * 3;

    for (int t = 0; t < T; ++t) {
        // Prefetch + premultiply next step's forcing terms (hidden under MUFU).
        int tn = (t + 1 < T) ? (t + 1) : (T - 1);
        float To_n = __ldg(ext + (size_t)tn * 3 + 0);
        float hp_n = __ldg(ext + (size_t)tn * 3 + 1);
        float sg_n = __ldg(ext + (size_t)tn * 3 + 2);

        // dT terms (dependent chain starts here).
        float d_ie = Tin - Te;
        float d_ih = Tin - Th;
        float d_oe = To  - Te;
        float x0 = fmaf(d_ie, nkA, fmaf(d_ih, nkB, sk));  // dT_in
        float x1 = fmaf(d_ih, kC,  hk);                    // dT_heater
        float x2 = fmaf(d_ie, kD,  d_oe * kE);             // dT_env

        // tame(x) = (x*TAME) * rsqrt(x^2 + TAME^2); x*TAME overlaps the MUFU.
        float r0 = rsq_approx(fmaf(x0, x0, TAME_SQ));
        float r1 = rsq_approx(fmaf(x1, x1, TAME_SQ));
        float r2 = rsq_approx(fmaf(x2, x2, TAME_SQ));
        Tin = fmaf(x0 * TAME_C, r0, Tin);
        Th  = fmaf(x1 * TAME_C, r1, Th);
        Te  = fmaf(x2 * TAME_C, r2, Te);

        // Trajectory store (fire-and-forget, off chain).
        op[0] = Tin;
        op[1] = Th;
        op[2] = Te;
        op += stride;

        To = To_n;
        sk = sg_n * k1;
        hk = hp_n * k2;
    }
}

extern "C" void kernel_launch(void* const* d_in, const int* in_sizes, int n_in,
                              void* d_out, int out_size)
{
    const float* state0 = (const float*)d_in[0];   // (B,3)
    const float* params = (const float*)d_in[1];   // (B,6)
    const float* ext    = (const float*)d_in[2];   // (T,3)
    const int*   dtp    = (const int*)d_in[3];     // scalar
    float* out = (float*)d_out;                    // (T,B,3)

    int B = in_sizes[0] / 3;
    int T = in_sizes[2] / 3;

    dim3 block(32);
    dim3 grid((B + 31) / 32);
    tithte_kernel<<<grid, block>>>(state0, params, ext, dtp, out, B, T);
}

// round 6
// speedup vs baseline: 1.7477x; 1.7477x over previous
#include <cuda_runtime.h>
#include <cuda_bf16.h>
#include <cstdint>

// TiThTe: B=4096 independent 3-state RC thermal ODEs, sequential Euler scan
// over T=8760 steps with tame() soft-clip. Latency-bound on the per-step
// dependent chain (1 warp/SM). This version:
//  - coefficient-form linear combine (tree depth 8-12, no serial sub chain)
//  - 4-step unroll; ext rows fetched as 3x LDG.128 per block, prefetched
//    2 blocks (8 steps) ahead -> L2 latency fully hidden, zero per-step
//    address math on the chain
//  - MUFU rsqrt with x*TAME overlapped; streaming stores (__stcs)

#define TAME_C  100000.0f
#define TAME_SQ 1.0e10f

__device__ __forceinline__ float rsq_approx(float x) {
    float y;
    asm("rsqrt.approx.f32 %0, %1;" : "=f"(y) : "f"(x));
    return y;
}

__global__ void __launch_bounds__(32, 1)
tithte_kernel(const float* __restrict__ state0,
              const float* __restrict__ params,
              const float* __restrict__ ext,     // (T,3): T_out, heatPower, solarGains
              const int*   __restrict__ dtp,
              float* __restrict__ out,           // (T,B,3)
              int B, int T)
{
    int b = blockIdx.x * blockDim.x + threadIdx.x;
    if (b >= B) return;

    int dv = dtp[0];
    float dtf = (dv > 0 && dv < (1 << 23)) ? (float)dv : __int_as_float(dv);

    float Tin = state0[b * 3 + 0];
    float Th  = state0[b * 3 + 1];
    float Te  = state0[b * 3 + 2];

    float C1 = params[b * 6 + 0], R1 = params[b * 6 + 1];
    float C2 = params[b * 6 + 2], R2 = params[b * 6 + 3];
    float C3 = params[b * 6 + 4], R3 = params[b * 6 + 5];

    // Coefficient form:
    //  x0 = cA0*Tin + cH0*Th + cE0*Te + sg*k1
    //  x1 =  kC*Tin + nkC*Th          + hp*k2
    //  x2 =  kD*Tin + cE2*Te          + To*kE
    float k1  = dtf / C1;
    float nkA = -k1 / R1;
    float nkB = -k1 / R2;
    float cA0 = nkA + nkB;
    float cH0 = -nkB;
    float cE0 = -nkA;
    float k2  = dtf / C2;
    float kC  =  k2 / R2;
    float nkC = -kC;
    float k3  = dtf / C3;
    float kD  =  k3 / R1;
    float kE  =  k3 / R3;
    float cE2 = -(kD + kE);

    float* op = out + (size_t)b * 3;
    const size_t stride = (size_t)B * 3;

#define STEP(To_, hp_, sg_)                                   \
    {                                                         \
        float f0 = (sg_) * k1;                                \
        float f1 = (hp_) * k2;                                \
        float f2 = (To_) * kE;                                \
        float u0 = fmaf(Tin, cA0, f0);                        \
        float v0 = fmaf(Th, cH0, Te * cE0);                   \
        float x0 = u0 + v0;                                   \
        float x1 = fmaf(Th, nkC, fmaf(Tin, kC, f1));          \
        float x2 = fmaf(Te, cE2, fmaf(Tin, kD, f2));          \
        float r0 = rsq_approx(fmaf(x0, x0, TAME_SQ));         \
        float r1 = rsq_approx(fmaf(x1, x1, TAME_SQ));         \
        float r2 = rsq_approx(fmaf(x2, x2, TAME_SQ));         \
        Tin = fmaf(x0 * TAME_C, r0, Tin);                     \
        Th  = fmaf(x1 * TAME_C, r1, Th);                      \
        Te  = fmaf(x2 * TAME_C, r2, Te);                      \
        __stcs(op + 0, Tin);                                  \
        __stcs(op + 1, Th);                                   \
        __stcs(op + 2, Te);                                   \
        op += stride;                                         \
    }

    int nb = T >> 2;            // 4-step blocks (T=8760 -> 2190)
    if (nb > 0) {
        const float4* e4 = (const float4*)ext;   // 4 rows = 12 floats = 3 float4

        float4 c0 = __ldg(e4 + 0), c1 = __ldg(e4 + 1), c2 = __ldg(e4 + 2);
        int j1 = (nb > 1) ? 3 : 0;
        float4 n0 = __ldg(e4 + j1), n1 = __ldg(e4 + j1 + 1), n2 = __ldg(e4 + j1 + 2);

        for (int blk = 0; blk < nb; ++blk) {
            int pfb = blk + 2; if (pfb > nb - 1) pfb = nb - 1;
            const float4* pp = e4 + (size_t)pfb * 3;
            float4 p0 = __ldg(pp), p1 = __ldg(pp + 1), p2 = __ldg(pp + 2);

            STEP(c0.x, c0.y, c0.z);
            STEP(c0.w, c1.x, c1.y);
            STEP(c1.z, c1.w, c2.x);
            STEP(c2.y, c2.z, c2.w);

            c0 = n0; c1 = n1; c2 = n2;
            n0 = p0; n1 = p1; n2 = p2;
        }
    }

    // Tail (T % 4 != 0) — not exercised for T=8760, kept for generality.
    for (int t = nb << 2; t < T; ++t) {
        float To = __ldg(ext + (size_t)t * 3 + 0);
        float hp = __ldg(ext + (size_t)t * 3 + 1);
        float sg = __ldg(ext + (size_t)t * 3 + 2);
        STEP(To, hp, sg);
    }
#undef STEP
}

extern "C" void kernel_launch(void* const* d_in, const int* in_sizes, int n_in,
                              void* d_out, int out_size)
{
    const float* state0 = (const float*)d_in[0];   // (B,3)
    const float* params = (const float*)d_in[1];   // (B,6)
    const float* ext    = (const float*)d_in[2];   // (T,3)
    const int*   dtp    = (const int*)d_in[3];     // scalar
    float* out = (float*)d_out;                    // (T,B,3)

    int B = in_sizes[0] / 3;
    int T = in_sizes[2] / 3;

    dim3 block(32);
    dim3 grid((B + 31) / 32);
    tithte_kernel<<<grid, block>>>(state0, params, ext, dtp, out, B, T);
}